// round 16
// baseline (speedup 1.0000x reference)
#include <cuda_runtime.h>

#define BB 8
#define NQV 4096
#define NKV 4096
#define CC 256
#define KNN 16
#define HH 32
#define EPSV 1e-5f
#define FINF 3.402823466e38f
#define FULLM 0xFFFFFFFFu

// Scratch (device globals: allocation-free rule)
__device__ float    g_kvproj[BB * NKV * HH];   // s1 * (kv_feat @ w1a^T)
__device__ float    g_qterm [BB * NQV * HH];   // s1 * (q_feat @ (w1b-w1a)^T) + t1
__device__ unsigned g_topk  [BB * NQV * KNN];  // neighbor indices
__device__ float4   g_pts   [BB * NKV];        // packed {x,y,z,|k|^2}

// ---------------------------------------------------------------------------
// Pack kv points once: {x,y,z,|k|^2} -> coalesced float4 array (L1-friendly).
// ---------------------------------------------------------------------------
__global__ void pack_kernel(const float* __restrict__ kxyz) {
    const int i = blockIdx.x * 512 + threadIdx.x;   // 64 x 512 = 32768
    const float x = kxyz[(size_t)i * 3 + 0];
    const float y = kxyz[(size_t)i * 3 + 1];
    const float z = kxyz[(size_t)i * 3 + 2];
    g_pts[i] = make_float4(x, y, z, x * x + y * y + z * z);
}

// ---------------------------------------------------------------------------
// Insert all balloted candidates into the 32-lane-distributed sorted list.
// LAZY TAU (R14-validated): a candidate >= current 16th sorts to position
// >= 16 and never perturbs lanes 0..15. Ballot order (ffs) = index order,
// so tie semantics (strict <, earliest index wins) match stable top_k.
// ---------------------------------------------------------------------------
__device__ __forceinline__ void insert_fires(
    float d, int tb, int lane, float& s, unsigned& si, float tau)
{
    unsigned m = __ballot_sync(FULLM, d < tau);
    while (m) {
        const int src = __ffs(m) - 1;
        m &= m - 1;
        const float    dv = __shfl_sync(FULLM, d, src);
        const unsigned iv = (unsigned)(tb + src);
        float    s_up = __shfl_up_sync(FULLM, s, 1);
        unsigned i_up = __shfl_up_sync(FULLM, si, 1);
        if (lane == 0) s_up = -FINF;
        if (s > dv) {
            si = (s_up > dv) ? i_up : iv;
            s  = fmaxf(s_up, dv);
        }
    }
}

// ---------------------------------------------------------------------------
// topk tile body (R12/R14-validated): two queries per warp, fused fast-path
// ballot, lazy-tau inserts. Ranking key d = |k|^2 - 2 q.k (exact).
// ---------------------------------------------------------------------------
__device__ __forceinline__ void topk_body(int blk, const float* __restrict__ qxyz)
{
    const int w    = (blk * 512 + (int)threadIdx.x) >> 5;    // logical warp id
    const int lane = threadIdx.x & 31;
    const int qa   = w * 2;
    const int b    = qa >> 12;

    const float aqx = qxyz[(size_t)qa * 3 + 0];
    const float aqy = qxyz[(size_t)qa * 3 + 1];
    const float aqz = qxyz[(size_t)qa * 3 + 2];
    const float bqx = qxyz[(size_t)(qa + 1) * 3 + 0];
    const float bqy = qxyz[(size_t)(qa + 1) * 3 + 1];
    const float bqz = qxyz[(size_t)(qa + 1) * 3 + 2];
    const float axa = -2.0f * aqx, aya = -2.0f * aqy, aza = -2.0f * aqz;
    const float axb = -2.0f * bqx, ayb = -2.0f * bqy, azb = -2.0f * bqz;

    const float4* pts = g_pts + (size_t)b * NKV;

    float    sa = FINF, sb = FINF;
    unsigned ia = 0,    ib = 0;
    float    taua = FINF, taub = FINF;

    for (int t = 0; t < NKV; t += 64) {
        const float4 p0 = __ldg(&pts[t + lane]);
        const float4 p1 = __ldg(&pts[t + 32 + lane]);

        float da0 = fmaf(axa, p0.x, p0.w);
        da0 = fmaf(aya, p0.y, da0);
        da0 = fmaf(aza, p0.z, da0);
        float db0 = fmaf(axb, p0.x, p0.w);
        db0 = fmaf(ayb, p0.y, db0);
        db0 = fmaf(azb, p0.z, db0);
        float da1 = fmaf(axa, p1.x, p1.w);
        da1 = fmaf(aya, p1.y, da1);
        da1 = fmaf(aza, p1.z, da1);
        float db1 = fmaf(axb, p1.x, p1.w);
        db1 = fmaf(ayb, p1.y, db1);
        db1 = fmaf(azb, p1.z, db1);

        const bool anyf = (da0 < taua) | (db0 < taub) | (da1 < taua) | (db1 < taub);
        if (__ballot_sync(FULLM, anyf)) {
            insert_fires(da0, t,      lane, sa, ia, taua);
            insert_fires(da1, t + 32, lane, sa, ia, taua);
            insert_fires(db0, t,      lane, sb, ib, taub);
            insert_fires(db1, t + 32, lane, sb, ib, taub);
            taua = __shfl_sync(FULLM, sa, 15);
            taub = __shfl_sync(FULLM, sb, 15);
        }
    }

    if (lane < KNN) {
        g_topk[(size_t)qa * KNN + lane] = ia;
        g_topk[(size_t)(qa + 1) * KNN + lane] = ib;
    }
}

// ---------------------------------------------------------------------------
// proj tile body: 256 rows x 32 h per block, 512 threads, 16 outs/thread
// (4m x 4h). Numerically identical inner loop/epilogue to the validated proj.
//   mode 0: W = w1[h][c]            -> g_kvproj, epilogue *= s1[h]
//   mode 1: W = w1[h][C+c]-w1[h][c] -> g_qterm,  epilogue = acc*s1[h] + t1[h]
// ---------------------------------------------------------------------------
__device__ __forceinline__ void proj_body(
    int pid, const float* __restrict__ kvf, const float* __restrict__ qf,
    const float* __restrict__ w1,
    const float* __restrict__ g1, const float* __restrict__ b1,
    const float* __restrict__ m1, const float* __restrict__ v1)
{
    __shared__ float AsubT[32][260];  // [k][m], padded (33.3KB)
    __shared__ float WT[32][36];      // [k][h], padded

    const int tid  = threadIdx.x;
    const int mode = pid >> 7;                 // 128 blocks per mode
    const float* feat = mode ? qf : kvf;
    const int row0 = (pid & 127) * 256;
    const int h0   = (tid & 7) * 4;
    const int m0   = (tid >> 3) * 4;           // 0..63 -> 256 rows

    float acc[4][4];
#pragma unroll
    for (int i = 0; i < 4; ++i)
#pragma unroll
        for (int j = 0; j < 4; ++j) acc[i][j] = 0.0f;

    for (int k0 = 0; k0 < CC; k0 += 32) {
        {
            const int q4 = (tid & 7) * 4;
            const int r  = tid >> 3;           // 0..63
#pragma unroll
            for (int j = 0; j < 4; ++j) {
                const int row = r + j * 64;
                const float4 v = *(const float4*)(feat + (size_t)(row0 + row) * CC + k0 + q4);
                AsubT[q4 + 0][row] = v.x;
                AsubT[q4 + 1][row] = v.y;
                AsubT[q4 + 2][row] = v.z;
                AsubT[q4 + 3][row] = v.w;
            }
        }
        {
            const int kk = tid & 31;
            const int hb = tid >> 5;           // 0..15
#pragma unroll
            for (int j = 0; j < 2; ++j) {
                const int hh = hb + j * 16;
                float w = w1[hh * (2 * CC) + k0 + kk];
                if (mode) w = w1[hh * (2 * CC) + CC + k0 + kk] - w;
                WT[kk][hh] = w;
            }
        }
        __syncthreads();
#pragma unroll
        for (int kk = 0; kk < 32; ++kk) {
            const float4 a = *(const float4*)&AsubT[kk][m0];
            const float4 w = *(const float4*)&WT[kk][h0];
            const float av[4] = {a.x, a.y, a.z, a.w};
            const float wv[4] = {w.x, w.y, w.z, w.w};
#pragma unroll
            for (int i = 0; i < 4; ++i)
#pragma unroll
                for (int j = 0; j < 4; ++j)
                    acc[i][j] = fmaf(av[i], wv[j], acc[i][j]);
        }
        __syncthreads();
    }

    float sv[4], tv[4];
#pragma unroll
    for (int j = 0; j < 4; ++j) {
        const int h = h0 + j;
        const float sc = g1[h] * rsqrtf(v1[h] + EPSV);
        sv[j] = sc;
        tv[j] = mode ? (b1[h] - m1[h] * sc) : 0.0f;
    }
    float* out = mode ? g_qterm : g_kvproj;
#pragma unroll
    for (int i = 0; i < 4; ++i) {
        float4 o;
        o.x = fmaf(acc[i][0], sv[0], tv[0]);
        o.y = fmaf(acc[i][1], sv[1], tv[1]);
        o.z = fmaf(acc[i][2], sv[2], tv[2]);
        o.w = fmaf(acc[i][3], sv[3], tv[3]);
        *(float4*)(out + (size_t)(row0 + m0 + i) * HH + h0) = o;
    }
}

// ---------------------------------------------------------------------------
// Combined kernel: heterogeneous block roles so MIO-bound topk blocks and
// FMA-bound proj blocks CO-RESIDE on each SM (their pipe usage is disjoint;
// per-SM issue approaches the sum of both). 1280 blocks: every 5th is proj
// (256 total), the rest topk (1024 total). Roles are independent (topk reads
// g_pts/qxyz; proj reads features) -- no intra-kernel ordering needed.
// ---------------------------------------------------------------------------
extern "C" __global__ __launch_bounds__(512, 2) void tp_kernel(
    const float* __restrict__ qxyz,
    const float* __restrict__ kvf, const float* __restrict__ qf,
    const float* __restrict__ w1,
    const float* __restrict__ g1, const float* __restrict__ b1,
    const float* __restrict__ m1, const float* __restrict__ v1)
{
    const int bi  = blockIdx.x;
    const int grp = bi / 5;
    const int rem = bi - grp * 5;
    if (rem == 4) {
        proj_body(grp, kvf, qf, w1, g1, b1, m1, v1);
    } else {
        topk_body(grp * 4 + rem, qxyz);
    }
}

// ---------------------------------------------------------------------------
// Kernel C: gather + add + leaky + max over K, then y = max @ w2^T + BN2 + leaky
// 512 threads/block, 64 queries, acc[4][8]. (unchanged, known-good)
// ---------------------------------------------------------------------------
__global__ __launch_bounds__(512) void fuse_kernel(
    const float* __restrict__ w2, const float* __restrict__ g2,
    const float* __restrict__ b2, const float* __restrict__ m2,
    const float* __restrict__ v2, float* __restrict__ out)
{
    __shared__ float w2t[HH][260];    // transposed w2, padded
    __shared__ float smaxT[HH][68];   // [h][q_local]
    __shared__ float s2s[CC], t2s[CC];

    const int tid = threadIdx.x;

    for (int idx = tid; idx < CC * HH; idx += 512) {
        const int c = idx >> 5, h = idx & 31;
        w2t[h][c] = w2[idx];
    }
    if (tid < 256) {
        const float sc = g2[tid] * rsqrtf(v2[tid] + EPSV);
        s2s[tid] = sc;
        t2s[tid] = b2[tid] - m2[tid] * sc;
    }

    const int r0   = blockIdx.x * 64;
    const int b    = r0 >> 12;
    const int warp = tid >> 5, lane = tid & 31;
    const float* kvb = g_kvproj + (size_t)b * NKV * HH;

    for (int qi = warp * 4; qi < warp * 4 + 4; ++qi) {
        const int r = r0 + qi;
        const float qt = g_qterm[(size_t)r * HH + lane];
        const uint4* ip = (const uint4*)(g_topk + (size_t)r * KNN);
        const uint4 i0 = ip[0], i1 = ip[1], i2 = ip[2], i3 = ip[3];
        const unsigned id[16] = {i0.x, i0.y, i0.z, i0.w, i1.x, i1.y, i1.z, i1.w,
                                 i2.x, i2.y, i2.z, i2.w, i3.x, i3.y, i3.z, i3.w};
        float mx = -FINF;
#pragma unroll
        for (int k = 0; k < 16; ++k) {
            float v = kvb[(size_t)id[k] * HH + lane] + qt;
            v = fmaxf(v, 0.2f * v);  // leaky relu (slope < 1)
            mx = fmaxf(mx, v);
        }
        smaxT[lane][qi] = mx;
    }
    __syncthreads();

    const int q0 = (tid & 15) * 4;
    const int c0 = (tid >> 4) * 8;
    float acc[4][8];
#pragma unroll
    for (int i = 0; i < 4; ++i)
#pragma unroll
        for (int j = 0; j < 8; ++j) acc[i][j] = 0.0f;

#pragma unroll 8
    for (int kk = 0; kk < HH; ++kk) {
        const float4 a = *(const float4*)&smaxT[kk][q0];
        const float av[4] = {a.x, a.y, a.z, a.w};
        float bv[8];
        {
            const float4 t0 = *(const float4*)&w2t[kk][c0];
            const float4 t1 = *(const float4*)&w2t[kk][c0 + 4];
            bv[0] = t0.x; bv[1] = t0.y; bv[2] = t0.z; bv[3] = t0.w;
            bv[4] = t1.x; bv[5] = t1.y; bv[6] = t1.z; bv[7] = t1.w;
        }
#pragma unroll
        for (int i = 0; i < 4; ++i)
#pragma unroll
            for (int j = 0; j < 8; ++j)
                acc[i][j] = fmaf(av[i], bv[j], acc[i][j]);
    }

#pragma unroll
    for (int i = 0; i < 4; ++i) {
        const int r = r0 + q0 + i;
        float* op = out + (size_t)r * CC + c0;
#pragma unroll
        for (int j4 = 0; j4 < 2; ++j4) {
            float4 o;
            float y;
            y = fmaf(acc[i][j4 * 4 + 0], s2s[c0 + j4 * 4 + 0], t2s[c0 + j4 * 4 + 0]); o.x = fmaxf(y, 0.2f * y);
            y = fmaf(acc[i][j4 * 4 + 1], s2s[c0 + j4 * 4 + 1], t2s[c0 + j4 * 4 + 1]); o.y = fmaxf(y, 0.2f * y);
            y = fmaf(acc[i][j4 * 4 + 2], s2s[c0 + j4 * 4 + 2], t2s[c0 + j4 * 4 + 2]); o.z = fmaxf(y, 0.2f * y);
            y = fmaf(acc[i][j4 * 4 + 3], s2s[c0 + j4 * 4 + 3], t2s[c0 + j4 * 4 + 3]); o.w = fmaxf(y, 0.2f * y);
            *(float4*)(op + j4 * 4) = o;
        }
    }
}

// ---------------------------------------------------------------------------
extern "C" void kernel_launch(void* const* d_in, const int* in_sizes, int n_in,
                              void* d_out, int out_size)
{
    const float* qf   = (const float*)d_in[0];   // (8,4096,256)
    const float* qxyz = (const float*)d_in[1];   // (8,4096,3)
    const float* kvf  = (const float*)d_in[2];   // (8,4096,256)
    const float* kxyz = (const float*)d_in[3];   // (8,4096,3)
    const float* w1   = (const float*)d_in[4];   // (32,512)
    const float* g1   = (const float*)d_in[5];
    const float* b1   = (const float*)d_in[6];
    const float* m1   = (const float*)d_in[7];
    const float* v1   = (const float*)d_in[8];
    const float* w2   = (const float*)d_in[9];   // (256,32)
    const float* g2   = (const float*)d_in[10];
    const float* b2   = (const float*)d_in[11];
    const float* m2   = (const float*)d_in[12];
    const float* v2   = (const float*)d_in[13];
    float* out = (float*)d_out;

    pack_kernel<<<64, 512>>>(kxyz);
    tp_kernel<<<1280, 512>>>(qxyz, kvf, qf, w1, g1, b1, m1, v1);
    fuse_kernel<<<512, 512>>>(w2, g2, b2, m2, v2, out);
}

// round 17
// speedup vs baseline: 1.0737x; 1.0737x over previous
#include <cuda_runtime.h>

#define BB 8
#define NQV 4096
#define NKV 4096
#define CC 256
#define KNN 16
#define HH 32
#define EPSV 1e-5f
#define FINF 3.402823466e38f
#define FULLM 0xFFFFFFFFu

// Scratch (device globals: allocation-free rule)
__device__ float    g_kvproj[BB * NKV * HH];   // s1 * (kv_feat @ w1a^T)
__device__ float    g_qterm [BB * NQV * HH];   // s1 * (q_feat @ (w1b-w1a)^T) + t1
__device__ unsigned g_topk  [BB * NQV * KNN];  // neighbor indices
__device__ float4   g_pts   [BB * NKV];        // packed {x,y,z,|k|^2}

// ---------------------------------------------------------------------------
// Pack kv points once: {x,y,z,|k|^2} -> coalesced float4 array.
// ---------------------------------------------------------------------------
__global__ void pack_kernel(const float* __restrict__ kxyz) {
    const int i = blockIdx.x * 512 + threadIdx.x;   // 64 x 512 = 32768
    const float x = kxyz[(size_t)i * 3 + 0];
    const float y = kxyz[(size_t)i * 3 + 1];
    const float z = kxyz[(size_t)i * 3 + 2];
    g_pts[i] = make_float4(x, y, z, x * x + y * y + z * z);
}

// ---------------------------------------------------------------------------
// Insert all balloted candidates into the 32-lane-distributed sorted list.
// LAZY TAU (R14-validated): a candidate >= current 16th sorts to position
// >= 16 and never perturbs lanes 0..15. Ballot order (ffs) = index order,
// so tie semantics (strict <, earliest index wins) match stable top_k.
// ---------------------------------------------------------------------------
__device__ __forceinline__ void insert_fires(
    float d, int tb, int lane, float& s, unsigned& si, float tau)
{
    unsigned m = __ballot_sync(FULLM, d < tau);
    while (m) {
        const int src = __ffs(m) - 1;
        m &= m - 1;
        const float    dv = __shfl_sync(FULLM, d, src);
        const unsigned iv = (unsigned)(tb + src);
        float    s_up = __shfl_up_sync(FULLM, s, 1);
        unsigned i_up = __shfl_up_sync(FULLM, si, 1);
        if (lane == 0) s_up = -FINF;
        if (s > dv) {
            si = (s_up > dv) ? i_up : iv;
            s  = fmaxf(s_up, dv);
        }
    }
}

// ---------------------------------------------------------------------------
// Kernel B: exact top-16 NN. TWO QUERIES PER WARP (R12/R14-validated body),
// with the batch's full 64KB point array STAGED IN SHARED MEMORY per block.
// This removes the L1-thrash -> L2-bandwidth bottleneck (each SM previously
// streamed all 8 batches' arrays from L2: ~1GB chip-wide; now 64MB once).
// 1024 blocks x 512 threads; 64KB dynamic smem -> 3 blocks/SM, 48 warps/SM.
// Ranking key d = |k|^2 - 2 q.k (|q|^2 dropped: exact).
// ---------------------------------------------------------------------------
extern "C" __global__ __launch_bounds__(512) void topk_kernel(
    const float* __restrict__ qxyz)
{
    extern __shared__ float4 s_pts[];   // 4096 x 16B = 64KB
    const int bi   = blockIdx.x;
    const int b    = bi >> 7;                       // 128 blocks per batch
    const int warp = threadIdx.x >> 5;
    const int lane = threadIdx.x & 31;
    const int qa   = bi * 32 + warp * 2;            // queries qa, qa+1

    // Stage the batch point array (coalesced float4)
    {
        const float4* gp = g_pts + (size_t)b * NKV;
        for (int i = threadIdx.x; i < NKV; i += 512) s_pts[i] = gp[i];
    }
    __syncthreads();

    const float aqx = qxyz[(size_t)qa * 3 + 0];
    const float aqy = qxyz[(size_t)qa * 3 + 1];
    const float aqz = qxyz[(size_t)qa * 3 + 2];
    const float bqx = qxyz[(size_t)(qa + 1) * 3 + 0];
    const float bqy = qxyz[(size_t)(qa + 1) * 3 + 1];
    const float bqz = qxyz[(size_t)(qa + 1) * 3 + 2];
    const float axa = -2.0f * aqx, aya = -2.0f * aqy, aza = -2.0f * aqz;
    const float axb = -2.0f * bqx, ayb = -2.0f * bqy, azb = -2.0f * bqz;

    float    sa = FINF, sb = FINF;     // 32-lane sorted list (lane i: i-th smallest)
    unsigned ia = 0,    ib = 0;
    float    taua = FINF, taub = FINF; // broadcast of s@lane15

    for (int t = 0; t < NKV; t += 64) {
        const float4 p0 = s_pts[t + lane];
        const float4 p1 = s_pts[t + 32 + lane];

        float da0 = fmaf(axa, p0.x, p0.w);
        da0 = fmaf(aya, p0.y, da0);
        da0 = fmaf(aza, p0.z, da0);
        float db0 = fmaf(axb, p0.x, p0.w);
        db0 = fmaf(ayb, p0.y, db0);
        db0 = fmaf(azb, p0.z, db0);
        float da1 = fmaf(axa, p1.x, p1.w);
        da1 = fmaf(aya, p1.y, da1);
        da1 = fmaf(aza, p1.z, da1);
        float db1 = fmaf(axb, p1.x, p1.w);
        db1 = fmaf(ayb, p1.y, db1);
        db1 = fmaf(azb, p1.z, db1);

        const bool anyf = (da0 < taua) | (db0 < taub) | (da1 < taua) | (db1 < taub);
        if (__ballot_sync(FULLM, anyf)) {
            insert_fires(da0, t,      lane, sa, ia, taua);
            insert_fires(da1, t + 32, lane, sa, ia, taua);
            insert_fires(db0, t,      lane, sb, ib, taub);
            insert_fires(db1, t + 32, lane, sb, ib, taub);
            taua = __shfl_sync(FULLM, sa, 15);
            taub = __shfl_sync(FULLM, sb, 15);
        }
    }

    if (lane < KNN) {
        g_topk[(size_t)qa * KNN + lane] = ia;
        g_topk[(size_t)(qa + 1) * KNN + lane] = ib;
    }
}

// ---------------------------------------------------------------------------
// Kernel A: projection GEMM, BOTH modes in one launch (mode = blockIdx.x>>8).
//   mode 0: W = w1[h][c]            -> g_kvproj, epilogue *= s1[h]
//   mode 1: W = w1[h][C+c]-w1[h][c] -> g_qterm,  epilogue = acc*s1[h] + t1[h]
// (exact R12/R14 version, known-good)
// ---------------------------------------------------------------------------
__global__ __launch_bounds__(256) void proj_kernel(
    const float* __restrict__ kvf, const float* __restrict__ qf,
    const float* __restrict__ w1,
    const float* __restrict__ g1, const float* __restrict__ b1,
    const float* __restrict__ m1, const float* __restrict__ v1)
{
    __shared__ float AsubT[32][132];
    __shared__ float WT[32][36];

    const int tid  = threadIdx.x;
    const int mode = blockIdx.x >> 8;
    const float* feat = mode ? qf : kvf;
    const int row0 = (blockIdx.x & 255) * 128;
    const int h0   = (tid & 7) * 4;
    const int m0   = (tid >> 3) * 4;

    float acc[4][4];
#pragma unroll
    for (int i = 0; i < 4; ++i)
#pragma unroll
        for (int j = 0; j < 4; ++j) acc[i][j] = 0.0f;

    for (int k0 = 0; k0 < CC; k0 += 32) {
        {
            const int q4 = (tid & 7) * 4;
            const int r  = tid >> 3;
#pragma unroll
            for (int j = 0; j < 4; ++j) {
                const int row = r + j * 32;
                const float4 v = *(const float4*)(feat + (size_t)(row0 + row) * CC + k0 + q4);
                AsubT[q4 + 0][row] = v.x;
                AsubT[q4 + 1][row] = v.y;
                AsubT[q4 + 2][row] = v.z;
                AsubT[q4 + 3][row] = v.w;
            }
        }
        {
            const int kk = tid & 31;
            const int hb = tid >> 5;
#pragma unroll
            for (int j = 0; j < 4; ++j) {
                const int hh = hb + j * 8;
                float w = w1[hh * (2 * CC) + k0 + kk];
                if (mode) w = w1[hh * (2 * CC) + CC + k0 + kk] - w;
                WT[kk][hh] = w;
            }
        }
        __syncthreads();
#pragma unroll
        for (int kk = 0; kk < 32; ++kk) {
            const float4 a = *(const float4*)&AsubT[kk][m0];
            const float4 w = *(const float4*)&WT[kk][h0];
            const float av[4] = {a.x, a.y, a.z, a.w};
            const float wv[4] = {w.x, w.y, w.z, w.w};
#pragma unroll
            for (int i = 0; i < 4; ++i)
#pragma unroll
                for (int j = 0; j < 4; ++j)
                    acc[i][j] = fmaf(av[i], wv[j], acc[i][j]);
        }
        __syncthreads();
    }

    float sv[4], tv[4];
#pragma unroll
    for (int j = 0; j < 4; ++j) {
        const int h = h0 + j;
        const float sc = g1[h] * rsqrtf(v1[h] + EPSV);
        sv[j] = sc;
        tv[j] = mode ? (b1[h] - m1[h] * sc) : 0.0f;
    }
    float* out = mode ? g_qterm : g_kvproj;
#pragma unroll
    for (int i = 0; i < 4; ++i) {
        float4 o;
        o.x = fmaf(acc[i][0], sv[0], tv[0]);
        o.y = fmaf(acc[i][1], sv[1], tv[1]);
        o.z = fmaf(acc[i][2], sv[2], tv[2]);
        o.w = fmaf(acc[i][3], sv[3], tv[3]);
        *(float4*)(out + (size_t)(row0 + m0 + i) * HH + h0) = o;
    }
}

// ---------------------------------------------------------------------------
// Kernel C: gather + add + leaky + max over K, then y = max @ w2^T + BN2 + leaky
// 512 threads/block, 64 queries, acc[4][8]. (unchanged, known-good)
// ---------------------------------------------------------------------------
__global__ __launch_bounds__(512) void fuse_kernel(
    const float* __restrict__ w2, const float* __restrict__ g2,
    const float* __restrict__ b2, const float* __restrict__ m2,
    const float* __restrict__ v2, float* __restrict__ out)
{
    __shared__ float w2t[HH][260];    // transposed w2, padded
    __shared__ float smaxT[HH][68];   // [h][q_local]
    __shared__ float s2s[CC], t2s[CC];

    const int tid = threadIdx.x;

    for (int idx = tid; idx < CC * HH; idx += 512) {
        const int c = idx >> 5, h = idx & 31;
        w2t[h][c] = w2[idx];
    }
    if (tid < 256) {
        const float sc = g2[tid] * rsqrtf(v2[tid] + EPSV);
        s2s[tid] = sc;
        t2s[tid] = b2[tid] - m2[tid] * sc;
    }

    const int r0   = blockIdx.x * 64;
    const int b    = r0 >> 12;
    const int warp = tid >> 5, lane = tid & 31;
    const float* kvb = g_kvproj + (size_t)b * NKV * HH;

    for (int qi = warp * 4; qi < warp * 4 + 4; ++qi) {
        const int r = r0 + qi;
        const float qt = g_qterm[(size_t)r * HH + lane];
        const uint4* ip = (const uint4*)(g_topk + (size_t)r * KNN);
        const uint4 i0 = ip[0], i1 = ip[1], i2 = ip[2], i3 = ip[3];
        const unsigned id[16] = {i0.x, i0.y, i0.z, i0.w, i1.x, i1.y, i1.z, i1.w,
                                 i2.x, i2.y, i2.z, i2.w, i3.x, i3.y, i3.z, i3.w};
        float mx = -FINF;
#pragma unroll
        for (int k = 0; k < 16; ++k) {
            float v = kvb[(size_t)id[k] * HH + lane] + qt;
            v = fmaxf(v, 0.2f * v);  // leaky relu (slope < 1)
            mx = fmaxf(mx, v);
        }
        smaxT[lane][qi] = mx;
    }
    __syncthreads();

    const int q0 = (tid & 15) * 4;
    const int c0 = (tid >> 4) * 8;
    float acc[4][8];
#pragma unroll
    for (int i = 0; i < 4; ++i)
#pragma unroll
        for (int j = 0; j < 8; ++j) acc[i][j] = 0.0f;

#pragma unroll 8
    for (int kk = 0; kk < HH; ++kk) {
        const float4 a = *(const float4*)&smaxT[kk][q0];
        const float av[4] = {a.x, a.y, a.z, a.w};
        float bv[8];
        {
            const float4 t0 = *(const float4*)&w2t[kk][c0];
            const float4 t1 = *(const float4*)&w2t[kk][c0 + 4];
            bv[0] = t0.x; bv[1] = t0.y; bv[2] = t0.z; bv[3] = t0.w;
            bv[4] = t1.x; bv[5] = t1.y; bv[6] = t1.z; bv[7] = t1.w;
        }
#pragma unroll
        for (int i = 0; i < 4; ++i)
#pragma unroll
            for (int j = 0; j < 8; ++j)
                acc[i][j] = fmaf(av[i], bv[j], acc[i][j]);
    }

#pragma unroll
    for (int i = 0; i < 4; ++i) {
        const int r = r0 + q0 + i;
        float* op = out + (size_t)r * CC + c0;
#pragma unroll
        for (int j4 = 0; j4 < 2; ++j4) {
            float4 o;
            float y;
            y = fmaf(acc[i][j4 * 4 + 0], s2s[c0 + j4 * 4 + 0], t2s[c0 + j4 * 4 + 0]); o.x = fmaxf(y, 0.2f * y);
            y = fmaf(acc[i][j4 * 4 + 1], s2s[c0 + j4 * 4 + 1], t2s[c0 + j4 * 4 + 1]); o.y = fmaxf(y, 0.2f * y);
            y = fmaf(acc[i][j4 * 4 + 2], s2s[c0 + j4 * 4 + 2], t2s[c0 + j4 * 4 + 2]); o.z = fmaxf(y, 0.2f * y);
            y = fmaf(acc[i][j4 * 4 + 3], s2s[c0 + j4 * 4 + 3], t2s[c0 + j4 * 4 + 3]); o.w = fmaxf(y, 0.2f * y);
            *(float4*)(op + j4 * 4) = o;
        }
    }
}

// ---------------------------------------------------------------------------
extern "C" void kernel_launch(void* const* d_in, const int* in_sizes, int n_in,
                              void* d_out, int out_size)
{
    const float* qf   = (const float*)d_in[0];   // (8,4096,256)
    const float* qxyz = (const float*)d_in[1];   // (8,4096,3)
    const float* kvf  = (const float*)d_in[2];   // (8,4096,256)
    const float* kxyz = (const float*)d_in[3];   // (8,4096,3)
    const float* w1   = (const float*)d_in[4];   // (32,512)
    const float* g1   = (const float*)d_in[5];
    const float* b1   = (const float*)d_in[6];
    const float* m1   = (const float*)d_in[7];
    const float* v1   = (const float*)d_in[8];
    const float* w2   = (const float*)d_in[9];   // (256,32)
    const float* g2   = (const float*)d_in[10];
    const float* b2   = (const float*)d_in[11];
    const float* m2   = (const float*)d_in[12];
    const float* v2   = (const float*)d_in[13];
    float* out = (float*)d_out;

    cudaFuncSetAttribute(topk_kernel, cudaFuncAttributeMaxDynamicSharedMemorySize, 65536);

    pack_kernel<<<64, 512>>>(kxyz);
    topk_kernel<<<1024, 512, 65536>>>(qxyz);
    proj_kernel<<<512, 256>>>(kvf, qf, w1, g1, b1, m1, v1);
    fuse_kernel<<<512, 512>>>(w2, g2, b2, m2, v2, out);
}